// round 4
// baseline (speedup 1.0000x reference)
#include <cuda_runtime.h>

#define NHEADS 8
#define NV     25
#define CI     64
#define CO     64
#define NBATCH 32
#define TT     256
#define DF     1600
#define MR     (NBATCH*TT)   /* 8192 */

// ---------------- scratch (static device globals; no allocs allowed) --------
__device__ float g_xf[MR*DF];                  // 52.4 MB  packed x: [n*T+t][c*V+v]
__device__ float g_mf[MR*DF];                  // 52.4 MB  packed m
__device__ float g_Kp[NHEADS*MR*DF];           // 419 MB   keys    [h][n*T+t][d]
__device__ float g_Qp[NHEADS*MR*DF];           // 419 MB   queries
__device__ float g_Vp[NHEADS*MR*DF];           // 419 MB   values
__device__ float g_Sp[NBATCH*NHEADS*TT*TT];    // 67 MB    scores  [(n*H+h)][q][t]

// ---------------- packed f32x2 helpers (Blackwell 2x fp32 path) -------------
__device__ __forceinline__ unsigned long long pack2(float a) {
    unsigned long long r;
    asm("mov.b64 %0, {%1, %1};" : "=l"(r) : "f"(a));
    return r;
}
__device__ __forceinline__ float2 unpack2(unsigned long long v) {
    float2 r;
    asm("mov.b64 {%0, %1}, %2;" : "=f"(r.x), "=f"(r.y) : "l"(v));
    return r;
}
__device__ __forceinline__ void fma2(unsigned long long& d,
                                     unsigned long long a, unsigned long long b) {
    asm("fma.rn.f32x2 %0, %1, %2, %0;" : "+l"(d) : "l"(a), "l"(b));
}

// 8x8 per-thread microtile on a 128x128x8 smem tile, accumulated as f32x2 pairs
__device__ __forceinline__ void mm_tile(const float (&As)[8][128],
                                        const float (&Bs)[8][128],
                                        unsigned long long (&acc)[8][4],
                                        int ty, int tx) {
#pragma unroll
    for (int kk = 0; kk < 8; kk++) {
        float4 a0 = *reinterpret_cast<const float4*>(&As[kk][ty * 8]);
        float4 a1 = *reinterpret_cast<const float4*>(&As[kk][ty * 8 + 4]);
        ulonglong2 b0 = *reinterpret_cast<const ulonglong2*>(&Bs[kk][tx * 8]);
        ulonglong2 b1 = *reinterpret_cast<const ulonglong2*>(&Bs[kk][tx * 8 + 4]);
        unsigned long long ap[8] = {pack2(a0.x), pack2(a0.y), pack2(a0.z), pack2(a0.w),
                                    pack2(a1.x), pack2(a1.y), pack2(a1.z), pack2(a1.w)};
        unsigned long long bp[4] = {b0.x, b0.y, b1.x, b1.y};
#pragma unroll
        for (int i = 0; i < 8; i++)
#pragma unroll
            for (int j = 0; j < 4; j++)
                fma2(acc[i][j], ap[i], bp[j]);
    }
}

// ---------------- kernel 1: pack [n,c,t,v] -> [n*T+t][c*V+v] ----------------
__global__ void pack_kernel(const float* __restrict__ src, int sel) {
    int gid = blockIdx.x * blockDim.x + threadIdx.x;
    int r = gid / DF;            // n*T + t
    int f = gid - r * DF;        // c*V + v
    int n = r >> 8;
    int t = r & 255;
    int c = f / NV;
    int v = f - c * NV;
    float* dst = sel ? g_mf : g_xf;
    dst[gid] = src[(((size_t)n * CI + c) * TT + t) * NV + v];
}

// ---------------- kernel 2: per-head projection GEMM + bias -----------------
// C[h][m][o] = A[m][k] * W[h][k][o] + bias[h][o]
__global__ __launch_bounds__(256, 2)
void gemm_proj(int sel, const float* __restrict__ W, const float* __restrict__ bias) {
    const int h = blockIdx.z;
    const float* A  = (sel == 0) ? g_xf : g_mf;
    const float* B  = W + (size_t)h * DF * DF;
    const float* bh = bias + (size_t)h * DF;
    float* Ch = ((sel == 0) ? g_Kp : (sel == 1) ? g_Qp : g_Vp) + (size_t)h * MR * DF;

    __shared__ __align__(16) float As[8][128];
    __shared__ __align__(16) float Bs[8][128];

    const int tid  = threadIdx.x;
    const int row0 = blockIdx.y * 128;
    const int col0 = blockIdx.x * 128;
    const int aRow = tid >> 1, aK = (tid & 1) * 4;
    const int bK   = tid >> 5, bCol = (tid & 31) * 4;
    const int tx   = tid & 15, ty = tid >> 4;

    unsigned long long acc[8][4];
#pragma unroll
    for (int i = 0; i < 8; i++)
#pragma unroll
        for (int j = 0; j < 4; j++) acc[i][j] = 0ull;

    for (int k0 = 0; k0 < DF; k0 += 8) {
        float4 a4 = *reinterpret_cast<const float4*>(A + (size_t)(row0 + aRow) * DF + k0 + aK);
        As[aK + 0][aRow] = a4.x; As[aK + 1][aRow] = a4.y;
        As[aK + 2][aRow] = a4.z; As[aK + 3][aRow] = a4.w;
        int c = col0 + bCol;
        float4 b4 = make_float4(0.f, 0.f, 0.f, 0.f);
        if (c < DF) b4 = *reinterpret_cast<const float4*>(B + (size_t)(k0 + bK) * DF + c);
        *reinterpret_cast<float4*>(&Bs[bK][bCol]) = b4;
        __syncthreads();
        mm_tile(As, Bs, acc, ty, tx);
        __syncthreads();
    }

#pragma unroll
    for (int i = 0; i < 8; i++) {
        size_t rbase = (size_t)(row0 + ty * 8 + i) * DF;
#pragma unroll
        for (int j = 0; j < 4; j++) {
            int c = col0 + tx * 8 + j * 2;
            if (c < DF) {
                float2 p = unpack2(acc[i][j]);
                Ch[rbase + c]     = p.x + bh[c];
                Ch[rbase + c + 1] = p.y + bh[c + 1];
            }
        }
    }
}

// ---------------- kernel 3: scores S = scale * Q K^T per (n,h) --------------
__global__ __launch_bounds__(256, 2)
void gemm_scores() {
    const int z = blockIdx.z;            // z = n*8 + h  (matches S layout n*H+h)
    const int n = z >> 3, h = z & 7;
    const float* Aq = g_Qp + (size_t)h * MR * DF + (size_t)n * TT * DF;
    const float* Bk = g_Kp + (size_t)h * MR * DF + (size_t)n * TT * DF;
    float* Sc = g_Sp + (size_t)z * TT * TT;

    __shared__ __align__(16) float As[8][128];
    __shared__ __align__(16) float Bs[8][128];

    const int tid  = threadIdx.x;
    const int row0 = blockIdx.y * 128;
    const int col0 = blockIdx.x * 128;
    const int lRow = tid >> 1, lK = (tid & 1) * 4;
    const int tx   = tid & 15, ty = tid >> 4;

    unsigned long long acc[8][4];
#pragma unroll
    for (int i = 0; i < 8; i++)
#pragma unroll
        for (int j = 0; j < 4; j++) acc[i][j] = 0ull;

    for (int k0 = 0; k0 < DF; k0 += 8) {
        float4 a4 = *reinterpret_cast<const float4*>(Aq + (size_t)(row0 + lRow) * DF + k0 + lK);
        As[lK + 0][lRow] = a4.x; As[lK + 1][lRow] = a4.y;
        As[lK + 2][lRow] = a4.z; As[lK + 3][lRow] = a4.w;
        float4 b4 = *reinterpret_cast<const float4*>(Bk + (size_t)(col0 + lRow) * DF + k0 + lK);
        Bs[lK + 0][lRow] = b4.x; Bs[lK + 1][lRow] = b4.y;
        Bs[lK + 2][lRow] = b4.z; Bs[lK + 3][lRow] = b4.w;
        __syncthreads();
        mm_tile(As, Bs, acc, ty, tx);
        __syncthreads();
    }

    const float scale = 0.025f;          // 1/sqrt(1600)
#pragma unroll
    for (int i = 0; i < 8; i++) {
        int q = row0 + ty * 8 + i;
#pragma unroll
        for (int j = 0; j < 4; j++) {
            int t = col0 + tx * 8 + j * 2;
            float2 p = unpack2(acc[i][j]);
            Sc[(size_t)q * TT + t]     = p.x * scale;
            Sc[(size_t)q * TT + t + 1] = p.y * scale;
        }
    }
}

// ---------------- kernel 4: softmax over the HEADS axis ---------------------
__global__ void softmax_heads() {
    int gid = blockIdx.x * blockDim.x + threadIdx.x;   // over NBATCH*T*T
    int n  = gid >> 16;
    int qt = gid & 65535;
    size_t base = ((size_t)n * NHEADS << 16) + qt;
    float v[NHEADS];
    float mx = -1e30f;
#pragma unroll
    for (int h = 0; h < NHEADS; h++) {
        v[h] = g_Sp[base + ((size_t)h << 16)];
        mx = fmaxf(mx, v[h]);
    }
    float s = 0.f;
#pragma unroll
    for (int h = 0; h < NHEADS; h++) { v[h] = __expf(v[h] - mx); s += v[h]; }
    float inv = 1.f / s;
#pragma unroll
    for (int h = 0; h < NHEADS; h++) g_Sp[base + ((size_t)h << 16)] = v[h] * inv;
}

// ---------------- kernel 5: Y = att @ V, fused output permutation -----------
// out[n, c*H+h, q, v] = Y[n,h,q, v*64+c]
__global__ __launch_bounds__(256, 2)
void gemm_y(float* __restrict__ out) {
    const int z = blockIdx.z;
    const int n = z >> 3, h = z & 7;
    const float* Aa = g_Sp + (size_t)z * TT * TT;                           // 256x256
    const float* Bv = g_Vp + (size_t)h * MR * DF + (size_t)n * TT * DF;     // 256x1600

    __shared__ __align__(16) float As[8][128];
    __shared__ __align__(16) float Bs[8][128];

    const int tid  = threadIdx.x;
    const int row0 = blockIdx.y * 128;
    const int col0 = blockIdx.x * 128;
    const int aRow = tid >> 1, aK = (tid & 1) * 4;
    const int bK   = tid >> 5, bCol = (tid & 31) * 4;
    const int tx   = tid & 15, ty = tid >> 4;

    unsigned long long acc[8][4];
#pragma unroll
    for (int i = 0; i < 8; i++)
#pragma unroll
        for (int j = 0; j < 4; j++) acc[i][j] = 0ull;

    for (int k0 = 0; k0 < TT; k0 += 8) {
        float4 a4 = *reinterpret_cast<const float4*>(Aa + (size_t)(row0 + aRow) * TT + k0 + aK);
        As[aK + 0][aRow] = a4.x; As[aK + 1][aRow] = a4.y;
        As[aK + 2][aRow] = a4.z; As[aK + 3][aRow] = a4.w;
        int c = col0 + bCol;
        float4 b4 = make_float4(0.f, 0.f, 0.f, 0.f);
        if (c < DF) b4 = *reinterpret_cast<const float4*>(Bv + (size_t)(k0 + bK) * DF + c);
        *reinterpret_cast<float4*>(&Bs[bK][bCol]) = b4;
        __syncthreads();
        mm_tile(As, Bs, acc, ty, tx);
        __syncthreads();
    }

#pragma unroll
    for (int i = 0; i < 8; i++) {
        int q = row0 + ty * 8 + i;
#pragma unroll
        for (int j = 0; j < 4; j++) {
            int d = col0 + tx * 8 + j * 2;
            if (d < DF) {
                float2 p = unpack2(acc[i][j]);
                int v = d >> 6;          // d = v*64 + c
                int c = d & 63;          // c is even, so d+1 shares v
                size_t o = (size_t)n * (512 * TT * NV)
                         + (size_t)((c << 3) + h) * (TT * NV)
                         + (size_t)q * NV + v;
                out[o]               = p.x;
                out[o + 8 * TT * NV] = p.y;   // (c+1)*8+h
            }
        }
    }
}

// ---------------- launch ----------------------------------------------------
extern "C" void kernel_launch(void* const* d_in, const int* in_sizes, int n_in,
                              void* d_out, int out_size) {
    const float* x  = (const float*)d_in[0];
    const float* m  = (const float*)d_in[1];
    const float* Wk = (const float*)d_in[2];
    const float* bk = (const float*)d_in[3];
    const float* Wq = (const float*)d_in[4];
    const float* bq = (const float*)d_in[5];
    const float* Wv = (const float*)d_in[6];
    const float* bv = (const float*)d_in[7];
    float* out = (float*)d_out;

    pack_kernel<<<(MR * DF) / 256, 256>>>(x, 0);
    pack_kernel<<<(MR * DF) / 256, 256>>>(m, 1);

    dim3 gp(13, 64, NHEADS);                 // ceil(1600/128)=13, 8192/128=64
    gemm_proj<<<gp, 256>>>(0, Wk, bk);       // keys    <- xf
    gemm_proj<<<gp, 256>>>(1, Wq, bq);       // queries <- mf
    gemm_proj<<<gp, 256>>>(2, Wv, bv);       // values  <- mf

    gemm_scores<<<dim3(2, 2, NBATCH * NHEADS), 256>>>();
    softmax_heads<<<(NBATCH * TT * TT) / 256, 256>>>();
    gemm_y<<<dim3(13, 2, NBATCH * NHEADS), 256>>>(out);
}

// round 7
// speedup vs baseline: 2.4172x; 2.4172x over previous
#include <cuda_runtime.h>
#include <cstdint>

#define NHEADS 8
#define NV     25
#define CI     64
#define NBATCH 32
#define TT     256
#define DF     1600
#define MR     (NBATCH*TT)   /* 8192 */
#define NPADW  1664          /* weight rows padded to 13*128 */

// ---------------- scratch (static device globals; no allocs allowed) --------
__device__ float g_xf[MR*DF];                  // packed x, tf32-rounded, shuffled
__device__ float g_mf[MR*DF];                  // packed m, tf32-rounded, shuffled
__device__ float g_Wt[24*NPADW*DF];            // 256MB K-major weights, shuffled
__device__ float g_Kp[NHEADS*MR*DF];           // keys    [h][n*T+t][d]  (fp32)
__device__ float g_Qp[NHEADS*MR*DF];           // queries
__device__ float g_Vp[NHEADS*MR*DF];           // values
__device__ float g_Sp[NBATCH*NHEADS*TT*TT];    // scores  [(n*H+h)][q][t]

// ======================= small helpers =====================================
__device__ __forceinline__ float tf32r(float x) {
    uint32_t u;
    asm("cvt.rna.tf32.f32 %0, %1;" : "=r"(u) : "f"(x));
    return __uint_as_float(u);
}
// fragment-shuffled + swizzled position of k within a row whose (row&7)=row7.
// Within each 32-k chunk: value (tig=k%4, j=(k%32)/4) stored at
// float index (slot^row7)*2 + (j&1), slot = tig*4 + j/2.
__device__ __forceinline__ int shufpos(int k, int row7) {
    int chunk = k >> 5, kk = k & 31;
    int tig = kk & 3, j = kk >> 2;
    int slot = ((tig << 2) + (j >> 1)) ^ row7;
    return (chunk << 5) + (slot << 1) + (j & 1);
}
__device__ __forceinline__ void cp16(uint32_t dst, const float* src) {
    asm volatile("cp.async.cg.shared.global [%0], [%1], 16;"
                 :: "r"(dst), "l"(__cvta_generic_to_global(src)) : "memory");
}
__device__ __forceinline__ uint2 lds64(uint32_t addr) {
    uint2 r;
    asm volatile("ld.shared.v2.b32 {%0,%1}, [%2];" : "=r"(r.x), "=r"(r.y) : "r"(addr));
    return r;
}
__device__ __forceinline__ void mma8(float* c, uint32_t a0, uint32_t a1,
                                     uint32_t a2, uint32_t a3,
                                     uint32_t b0, uint32_t b1) {
    asm volatile("mma.sync.aligned.m16n8k8.row.col.f32.tf32.tf32.f32 "
                 "{%0,%1,%2,%3}, {%4,%5,%6,%7}, {%8,%9}, {%0,%1,%2,%3};"
                 : "+f"(c[0]), "+f"(c[1]), "+f"(c[2]), "+f"(c[3])
                 : "r"(a0), "r"(a1), "r"(a2), "r"(a3), "r"(b0), "r"(b1));
}

// ---------------- packed f32x2 helpers (fp32 attention path) ----------------
__device__ __forceinline__ unsigned long long pack2(float a) {
    unsigned long long r;
    asm("mov.b64 %0, {%1, %1};" : "=l"(r) : "f"(a));
    return r;
}
__device__ __forceinline__ float2 unpack2(unsigned long long v) {
    float2 r;
    asm("mov.b64 {%0, %1}, %2;" : "=f"(r.x), "=f"(r.y) : "l"(v));
    return r;
}
__device__ __forceinline__ void fma2(unsigned long long& d,
                                     unsigned long long a, unsigned long long b) {
    asm("fma.rn.f32x2 %0, %1, %2, %0;" : "+l"(d) : "l"(a), "l"(b));
}
__device__ __forceinline__ void mm_tile(const float (&As)[8][128],
                                        const float (&Bs)[8][128],
                                        unsigned long long (&acc)[8][4],
                                        int ty, int tx) {
#pragma unroll
    for (int kk = 0; kk < 8; kk++) {
        float4 a0 = *reinterpret_cast<const float4*>(&As[kk][ty * 8]);
        float4 a1 = *reinterpret_cast<const float4*>(&As[kk][ty * 8 + 4]);
        ulonglong2 b0 = *reinterpret_cast<const ulonglong2*>(&Bs[kk][tx * 8]);
        ulonglong2 b1 = *reinterpret_cast<const ulonglong2*>(&Bs[kk][tx * 8 + 4]);
        unsigned long long ap[8] = {pack2(a0.x), pack2(a0.y), pack2(a0.z), pack2(a0.w),
                                    pack2(a1.x), pack2(a1.y), pack2(a1.z), pack2(a1.w)};
        unsigned long long bp[4] = {b0.x, b0.y, b1.x, b1.y};
#pragma unroll
        for (int i = 0; i < 8; i++)
#pragma unroll
            for (int j = 0; j < 4; j++)
                fma2(acc[i][j], ap[i], bp[j]);
    }
}

// ---------------- kernel 1: pack + tf32 round + shuffle ---------------------
__global__ void pack_kernel(const float* __restrict__ src, int sel) {
    int gid = blockIdx.x * blockDim.x + threadIdx.x;
    int r = gid / DF;            // n*T + t  (row)
    int f = gid - r * DF;        // c*V + v  (k)
    int n = r >> 8, t = r & 255;
    int c = f / NV, v = f - c * NV;
    float val = src[(((size_t)n * CI + c) * TT + t) * NV + v];
    float* dst = sel ? g_mf : g_xf;
    dst[(size_t)r * DF + shufpos(f, r & 7)] = tf32r(val);
}

// ---------------- kernel 1b: W[h][k][o] -> g_Wt[z][o][shuf(k)] (tf32) -------
__global__ void transpose_w(const float* __restrict__ Wk,
                            const float* __restrict__ Wq,
                            const float* __restrict__ Wv) {
    const int z = blockIdx.z;
    const int g = z >> 3, h = z & 7;
    const float* W = ((g == 0) ? Wk : (g == 1) ? Wq : Wv) + (size_t)h * DF * DF;
    float* Wt = g_Wt + (size_t)z * NPADW * DF;
    __shared__ float t[32][33];
    int k0 = blockIdx.x * 32, o0 = blockIdx.y * 32;
#pragma unroll
    for (int i = threadIdx.y; i < 32; i += 8)
        t[i][threadIdx.x] = W[(size_t)(k0 + i) * DF + o0 + threadIdx.x];
    __syncthreads();
#pragma unroll
    for (int i = threadIdx.y; i < 32; i += 8) {
        int o = o0 + i, k = k0 + threadIdx.x;
        Wt[(size_t)o * DF + shufpos(k, o & 7)] = tf32r(t[threadIdx.x][i]);
    }
}

// ---------------- kernel 2: tf32 mma.sync projection GEMM -------------------
// 128x128x32 tiles, 3-stage cp.async, 8 warps (warp tile 32m x 64n).
#define PST 3
#define STB 32768            /* A 16KB + B 16KB per stage */
#define SMEM_DYN (PST*STB)

__global__ __launch_bounds__(256, 2)
void gemm_proj_mma(const float* __restrict__ bk, const float* __restrict__ bq,
                   const float* __restrict__ bv) {
    extern __shared__ char dsm[];
    const uint32_t smemBase = (uint32_t)__cvta_generic_to_shared(dsm);

    const int tid = threadIdx.x;
    const int w = tid >> 5, lane = tid & 31;
    const int g = lane >> 2, tig = lane & 3;
    const int wm = w & 3, wn = w >> 2;            // 4x2 warp grid
    const int z = blockIdx.z, gg = z >> 3, h = z & 7;
    const int n0 = blockIdx.x * 128, m0 = blockIdx.y * 128;

    const float* A = (gg == 0) ? g_xf : g_mf;
    const float* B = g_Wt + (size_t)z * NPADW * DF;
    float* C = ((gg == 0) ? g_Kp : (gg == 1) ? g_Qp : g_Vp) + (size_t)h * MR * DF;
    const float* bias = ((gg == 0) ? bk : (gg == 1) ? bq : bv) + (size_t)h * DF;

    // producer mapping: thread -> (row, 64B half of the 128B row)
    const int arow = tid >> 1;
    const int ac = (tid & 1) * 64;                // byte offset 0 / 64
    const float* srcA = A + (size_t)(m0 + arow) * DF + (ac >> 2);
    const float* srcB = B + (size_t)(n0 + arow) * DF + (ac >> 2);

    float acc[2][8][4];
#pragma unroll
    for (int mt = 0; mt < 2; mt++)
#pragma unroll
        for (int nt = 0; nt < 8; nt++)
#pragma unroll
            for (int i = 0; i < 4; i++) acc[mt][nt][i] = 0.f;

#define LOAD_STAGE(s, j) do {                                              \
        uint32_t dA = smemBase + (s) * STB + arow * 128 + ac;              \
        const float* pA = srcA + (j) * 32;                                 \
        const float* pB = srcB + (j) * 32;                                 \
        cp16(dA,        pA);     cp16(dA + 16,         pA + 4);            \
        cp16(dA + 32,   pA + 8); cp16(dA + 48,         pA + 12);           \
        cp16(dA + 16384,      pB);      cp16(dA + 16384 + 16, pB + 4);     \
        cp16(dA + 16384 + 32, pB + 8);  cp16(dA + 16384 + 48, pB + 12);    \
    } while (0)

    LOAD_STAGE(0, 0);
    asm volatile("cp.async.commit_group;" ::: "memory");
    LOAD_STAGE(1, 1);
    asm volatile("cp.async.commit_group;" ::: "memory");

    // per-warp precomputed lds addresses (offsets only; jt XOR folded per-iter)
    for (int j = 0; j < 50; j++) {
        asm volatile("cp.async.wait_group 1;" ::: "memory");
        __syncthreads();
        if (j + 2 < 50) LOAD_STAGE((j + 2) % PST, j + 2);
        asm volatile("cp.async.commit_group;" ::: "memory");

        const uint32_t sA = smemBase + (j % PST) * STB;
        const uint32_t sB = sA + 16384;
#pragma unroll
        for (int jt = 0; jt < 4; jt++) {
            uint2 ap[4];
#pragma unroll
            for (int r = 0; r < 4; r++) {
                int row = wm * 32 + (r & 1) * 8 + (r >> 1) * 16 + g;
                int off = ((((tig << 2) + jt) ^ (row & 7)) << 3);
                ap[r] = lds64(sA + row * 128 + off);
            }
            uint2 bp[8];
#pragma unroll
            for (int nt = 0; nt < 8; nt++) {
                int n = wn * 64 + nt * 8 + g;
                int off = ((((tig << 2) + jt) ^ (n & 7)) << 3);
                bp[nt] = lds64(sB + n * 128 + off);
            }
#pragma unroll
            for (int mt = 0; mt < 2; mt++)
#pragma unroll
                for (int nt = 0; nt < 8; nt++)
                    mma8(acc[mt][nt],
                         ap[2 * mt].x, ap[2 * mt + 1].x,
                         ap[2 * mt].y, ap[2 * mt + 1].y,
                         bp[nt].x, bp[nt].y);
        }
    }

    // ---------------- epilogue: bias + store --------------------------------
#pragma unroll
    for (int mt = 0; mt < 2; mt++) {
        int row = m0 + wm * 32 + mt * 16 + g;
        float* c0 = C + (size_t)row * DF;
        float* c1 = C + (size_t)(row + 8) * DF;
#pragma unroll
        for (int nt = 0; nt < 8; nt++) {
            int col = n0 + wn * 64 + nt * 8 + tig * 2;
            if (col < DF) {
                float b0v = bias[col], b1v = bias[col + 1];
                float2 v0 = make_float2(acc[mt][nt][0] + b0v, acc[mt][nt][1] + b1v);
                float2 v1 = make_float2(acc[mt][nt][2] + b0v, acc[mt][nt][3] + b1v);
                *reinterpret_cast<float2*>(c0 + col) = v0;
                *reinterpret_cast<float2*>(c1 + col) = v1;
            }
        }
    }
#undef LOAD_STAGE
}

// ---------------- kernel 3: scores S = scale * Q K^T per (n,h) --------------
__global__ __launch_bounds__(256, 2)
void gemm_scores() {
    const int z = blockIdx.z;
    const int n = z >> 3, h = z & 7;
    const float* Aq = g_Qp + (size_t)h * MR * DF + (size_t)n * TT * DF;
    const float* Bk = g_Kp + (size_t)h * MR * DF + (size_t)n * TT * DF;
    float* Sc = g_Sp + (size_t)z * TT * TT;

    __shared__ __align__(16) float As[8][128];
    __shared__ __align__(16) float Bs[8][128];

    const int tid  = threadIdx.x;
    const int row0 = blockIdx.y * 128;
    const int col0 = blockIdx.x * 128;
    const int lRow = tid >> 1, lK = (tid & 1) * 4;
    const int tx   = tid & 15, ty = tid >> 4;

    unsigned long long acc[8][4];
#pragma unroll
    for (int i = 0; i < 8; i++)
#pragma unroll
        for (int j = 0; j < 4; j++) acc[i][j] = 0ull;

    for (int k0 = 0; k0 < DF; k0 += 8) {
        float4 a4 = *reinterpret_cast<const float4*>(Aq + (size_t)(row0 + lRow) * DF + k0 + lK);
        As[lK + 0][lRow] = a4.x; As[lK + 1][lRow] = a4.y;
        As[lK + 2][lRow] = a4.z; As[lK + 3][lRow] = a4.w;
        float4 b4 = *reinterpret_cast<const float4*>(Bk + (size_t)(col0 + lRow) * DF + k0 + lK);
        Bs[lK + 0][lRow] = b4.x; Bs[lK + 1][lRow] = b4.y;
        Bs[lK + 2][lRow] = b4.z; Bs[lK + 3][lRow] = b4.w;
        __syncthreads();
        mm_tile(As, Bs, acc, ty, tx);
        __syncthreads();
    }

    const float scale = 0.025f;
#pragma unroll
    for (int i = 0; i < 8; i++) {
        int q = row0 + ty * 8 + i;
#pragma unroll
        for (int j = 0; j < 4; j++) {
            int t = col0 + tx * 8 + j * 2;
            float2 p = unpack2(acc[i][j]);
            Sc[(size_t)q * TT + t]     = p.x * scale;
            Sc[(size_t)q * TT + t + 1] = p.y * scale;
        }
    }
}

// ---------------- kernel 4: softmax over the HEADS axis ---------------------
__global__ void softmax_heads() {
    int gid = blockIdx.x * blockDim.x + threadIdx.x;
    int n  = gid >> 16;
    int qt = gid & 65535;
    size_t base = ((size_t)n * NHEADS << 16) + qt;
    float v[NHEADS];
    float mx = -1e30f;
#pragma unroll
    for (int h = 0; h < NHEADS; h++) {
        v[h] = g_Sp[base + ((size_t)h << 16)];
        mx = fmaxf(mx, v[h]);
    }
    float s = 0.f;
#pragma unroll
    for (int h = 0; h < NHEADS; h++) { v[h] = __expf(v[h] - mx); s += v[h]; }
    float inv = 1.f / s;
#pragma unroll
    for (int h = 0; h < NHEADS; h++) g_Sp[base + ((size_t)h << 16)] = v[h] * inv;
}

// ---------------- kernel 5: Y = att @ V, fused output permutation -----------
__global__ __launch_bounds__(256, 2)
void gemm_y(float* __restrict__ out) {
    const int z = blockIdx.z;
    const int n = z >> 3, h = z & 7;
    const float* Aa = g_Sp + (size_t)z * TT * TT;
    const float* Bv = g_Vp + (size_t)h * MR * DF + (size_t)n * TT * DF;

    __shared__ __align__(16) float As[8][128];
    __shared__ __align__(16) float Bs[8][128];

    const int tid  = threadIdx.x;
    const int row0 = blockIdx.y * 128;
    const int col0 = blockIdx.x * 128;
    const int aRow = tid >> 1, aK = (tid & 1) * 4;
    const int bK   = tid >> 5, bCol = (tid & 31) * 4;
    const int tx   = tid & 15, ty = tid >> 4;

    unsigned long long acc[8][4];
#pragma unroll
    for (int i = 0; i < 8; i++)
#pragma unroll
        for (int j = 0; j < 4; j++) acc[i][j] = 0ull;

    for (int k0 = 0; k0 < TT; k0 += 8) {
        float4 a4 = *reinterpret_cast<const float4*>(Aa + (size_t)(row0 + aRow) * TT + k0 + aK);
        As[aK + 0][aRow] = a4.x; As[aK + 1][aRow] = a4.y;
        As[aK + 2][aRow] = a4.z; As[aK + 3][aRow] = a4.w;
        int c = col0 + bCol;
        float4 b4 = make_float4(0.f, 0.f, 0.f, 0.f);
        if (c < DF) b4 = *reinterpret_cast<const float4*>(Bv + (size_t)(k0 + bK) * DF + c);
        *reinterpret_cast<float4*>(&Bs[bK][bCol]) = b4;
        __syncthreads();
        mm_tile(As, Bs, acc, ty, tx);
        __syncthreads();
    }

#pragma unroll
    for (int i = 0; i < 8; i++) {
        int q = row0 + ty * 8 + i;
#pragma unroll
        for (int j = 0; j < 4; j++) {
            int d = col0 + tx * 8 + j * 2;
            if (d < DF) {
                float2 p = unpack2(acc[i][j]);
                int v = d >> 6;
                int c = d & 63;
                size_t o = (size_t)n * (512 * TT * NV)
                         + (size_t)((c << 3) + h) * (TT * NV)
                         + (size_t)q * NV + v;
                out[o]               = p.x;
                out[o + 8 * TT * NV] = p.y;
            }
        }
    }
}

// ---------------- launch ----------------------------------------------------
extern "C" void kernel_launch(void* const* d_in, const int* in_sizes, int n_in,
                              void* d_out, int out_size) {
    const float* x  = (const float*)d_in[0];
    const float* m  = (const float*)d_in[1];
    const float* Wk = (const float*)d_in[2];
    const float* bk = (const float*)d_in[3];
    const float* Wq = (const float*)d_in[4];
    const float* bq = (const float*)d_in[5];
    const float* Wv = (const float*)d_in[6];
    const float* bv = (const float*)d_in[7];
    float* out = (float*)d_out;

    cudaFuncSetAttribute(gemm_proj_mma, cudaFuncAttributeMaxDynamicSharedMemorySize, SMEM_DYN);

    pack_kernel<<<(MR * DF) / 256, 256>>>(x, 0);
    pack_kernel<<<(MR * DF) / 256, 256>>>(m, 1);
    transpose_w<<<dim3(50, 50, 24), dim3(32, 8)>>>(Wk, Wq, Wv);

    // tf32 mma.sync projections: grid = (N-tiles, M-tiles, g*8+h)
    gemm_proj_mma<<<dim3(13, 64, 24), 256, SMEM_DYN>>>(bk, bq, bv);

    gemm_scores<<<dim3(2, 2, NBATCH * NHEADS), 256>>>();
    softmax_heads<<<(NBATCH * TT * TT) / 256, 256>>>();
    gemm_y<<<dim3(13, 2, NBATCH * NHEADS), 256>>>(out);
}

// round 9
// speedup vs baseline: 2.7706x; 1.1462x over previous
#include <cuda_runtime.h>
#include <cstdint>

#define NHEADS 8
#define NV     25
#define CI     64
#define NBATCH 32
#define TT     256
#define DF     1600
#define MR     (NBATCH*TT)   /* 8192 */
#define NPADW  1664          /* padded to 13*128 */

// ---------------- scratch (static device globals; no allocs allowed) --------
__device__ float g_xf[MR*DF];                  // packed x, tf32, shuffled
__device__ float g_mf[MR*DF];                  // packed m, tf32, shuffled
__device__ float g_Wt[24*NPADW*DF];            // K-major weights, tf32, shuffled
__device__ float g_Qs[NHEADS*MR*DF];           // queries [z=n*8+h][q][shuf(d)] tf32
__device__ float g_Ks[NHEADS*MR*DF];           // keys    same layout
__device__ float g_Vp[NHEADS*MR*DF];           // values  [h][m][d] plain fp32
__device__ float g_Vts[256*NPADW*TT];          // V^T [h*32+n][d(pad)][shuf(t)] tf32
__device__ float g_Sp[NBATCH*NHEADS*TT*TT];    // scores [z][q][t] fp32
__device__ float g_As[256*TT*TT];              // softmaxed att [z][q][shuf(t)] tf32

// ======================= helpers ===========================================
__device__ __forceinline__ float tf32r(float x) {
    uint32_t u;
    asm("cvt.rna.tf32.f32 %0, %1;" : "=r"(u) : "f"(x));
    return __uint_as_float(u);
}
// fragment-shuffled position of k within a row with parity row7 = row&7
__device__ __forceinline__ int shufpos(int k, int row7) {
    int chunk = k >> 5, kk = k & 31;
    int tig = kk & 3, j = kk >> 2;
    int slot = ((tig << 2) + (j >> 1)) ^ row7;
    return (chunk << 5) + (slot << 1) + (j & 1);
}
__device__ __forceinline__ void cp16(uint32_t dst, const float* src) {
    asm volatile("cp.async.cg.shared.global [%0], [%1], 16;"
                 :: "r"(dst), "l"(__cvta_generic_to_global(src)) : "memory");
}
__device__ __forceinline__ uint2 lds64(uint32_t addr) {
    uint2 r;
    asm volatile("ld.shared.v2.b32 {%0,%1}, [%2];" : "=r"(r.x), "=r"(r.y) : "r"(addr));
    return r;
}
__device__ __forceinline__ void mma8(float* c, uint32_t a0, uint32_t a1,
                                     uint32_t a2, uint32_t a3,
                                     uint32_t b0, uint32_t b1) {
    asm volatile("mma.sync.aligned.m16n8k8.row.col.f32.tf32.tf32.f32 "
                 "{%0,%1,%2,%3}, {%4,%5,%6,%7}, {%8,%9}, {%0,%1,%2,%3};"
                 : "+f"(c[0]), "+f"(c[1]), "+f"(c[2]), "+f"(c[3])
                 : "r"(a0), "r"(a1), "r"(a2), "r"(a3), "r"(b0), "r"(b1));
}

// ======================= shared tf32 GEMM mainloop ==========================
#define PST 3
#define STB 32768            /* A 16KB + B 16KB per stage */
#define SMEM_DYN (PST*STB)

__device__ __forceinline__ void load_stage(uint32_t smemBase, int s, int j,
                                           const float* pA0, const float* pB0,
                                           int arow, int ac) {
    uint32_t dA = smemBase + s * STB + arow * 128 + ac;
    const float* pA = pA0 + j * 32;
    const float* pB = pB0 + j * 32;
    cp16(dA,      pA);     cp16(dA + 16, pA + 4);
    cp16(dA + 32, pA + 8); cp16(dA + 48, pA + 12);
    uint32_t dB = dA + 16384;
    cp16(dB,      pB);     cp16(dB + 16, pB + 4);
    cp16(dB + 32, pB + 8); cp16(dB + 48, pB + 12);
}

template<int CH>
__device__ __forceinline__ void mm_mainloop(const float* tileA, int ldA,
                                            const float* tileB, int ldB,
                                            uint32_t smemBase, int tid,
                                            float (&acc)[2][8][4]) {
    const int lane = tid & 31, w = tid >> 5;
    const int g = lane >> 2, tig = lane & 3;
    const int wm = w & 3, wn = w >> 2;
    const int arow = tid >> 1, ac = (tid & 1) * 64;
    const float* pA0 = tileA + (size_t)arow * ldA + (ac >> 2);
    const float* pB0 = tileB + (size_t)arow * ldB + (ac >> 2);

    load_stage(smemBase, 0, 0, pA0, pB0, arow, ac);
    asm volatile("cp.async.commit_group;" ::: "memory");
    if (CH > 1) load_stage(smemBase, 1, 1, pA0, pB0, arow, ac);
    asm volatile("cp.async.commit_group;" ::: "memory");

    for (int j = 0; j < CH; j++) {
        asm volatile("cp.async.wait_group 1;" ::: "memory");
        __syncthreads();
        if (j + 2 < CH) load_stage(smemBase, (j + 2) % PST, j + 2, pA0, pB0, arow, ac);
        asm volatile("cp.async.commit_group;" ::: "memory");

        const uint32_t sA = smemBase + (j % PST) * STB;
        const uint32_t sB = sA + 16384;
#pragma unroll
        for (int jt = 0; jt < 4; jt++) {
            uint2 ap[4];
#pragma unroll
            for (int r = 0; r < 4; r++) {
                int row = wm * 32 + (r & 1) * 8 + (r >> 1) * 16 + g;
                int off = ((((tig << 2) + jt) ^ (row & 7)) << 3);
                ap[r] = lds64(sA + row * 128 + off);
            }
            uint2 bp[8];
#pragma unroll
            for (int nt = 0; nt < 8; nt++) {
                int n = wn * 64 + nt * 8 + g;
                int off = ((((tig << 2) + jt) ^ (n & 7)) << 3);
                bp[nt] = lds64(sB + n * 128 + off);
            }
#pragma unroll
            for (int mt = 0; mt < 2; mt++)
#pragma unroll
                for (int nt = 0; nt < 8; nt++)
                    mma8(acc[mt][nt],
                         ap[2 * mt].x, ap[2 * mt + 1].x,
                         ap[2 * mt].y, ap[2 * mt + 1].y,
                         bp[nt].x, bp[nt].y);
        }
    }
}

// ---------------- kernel 1: pack + tf32 round + shuffle ---------------------
__global__ void pack_kernel(const float* __restrict__ src, int sel) {
    int gid = blockIdx.x * blockDim.x + threadIdx.x;
    int r = gid / DF;
    int f = gid - r * DF;
    int n = r >> 8, t = r & 255;
    int c = f / NV, v = f - c * NV;
    float val = src[(((size_t)n * CI + c) * TT + t) * NV + v];
    float* dst = sel ? g_mf : g_xf;
    dst[(size_t)r * DF + shufpos(f, r & 7)] = tf32r(val);
}

// ---------------- kernel 1b: W[h][k][o] -> g_Wt[z][o][shuf(k)] --------------
__global__ void transpose_w(const float* __restrict__ Wk,
                            const float* __restrict__ Wq,
                            const float* __restrict__ Wv) {
    const int z = blockIdx.z;
    const int g = z >> 3, h = z & 7;
    const float* W = ((g == 0) ? Wk : (g == 1) ? Wq : Wv) + (size_t)h * DF * DF;
    float* Wt = g_Wt + (size_t)z * NPADW * DF;
    __shared__ float t[32][33];
    int k0 = blockIdx.x * 32, o0 = blockIdx.y * 32;
#pragma unroll
    for (int i = threadIdx.y; i < 32; i += 8)
        t[i][threadIdx.x] = W[(size_t)(k0 + i) * DF + o0 + threadIdx.x];
    __syncthreads();
#pragma unroll
    for (int i = threadIdx.y; i < 32; i += 8) {
        int o = o0 + i, k = k0 + threadIdx.x;
        Wt[(size_t)o * DF + shufpos(k, o & 7)] = tf32r(t[threadIdx.x][i]);
    }
}

// ---------------- kernel 2: projection GEMM (tf32 mma.sync) -----------------
// gg=0 -> K (shuffled), gg=1 -> Q (shuffled), gg=2 -> V (plain fp32)
__global__ __launch_bounds__(256, 2)
void gemm_proj_mma(const float* __restrict__ bk, const float* __restrict__ bq,
                   const float* __restrict__ bv) {
    extern __shared__ char dsm[];
    const uint32_t smemBase = (uint32_t)__cvta_generic_to_shared(dsm);
    const int tid = threadIdx.x;
    const int z = blockIdx.z, gg = z >> 3, h = z & 7;
    const int n0 = blockIdx.x * 128, m0 = blockIdx.y * 128;

    const float* A = (gg == 0) ? g_xf : g_mf;
    const float* B = g_Wt + (size_t)z * NPADW * DF;
    const float* bias = ((gg == 0) ? bk : (gg == 1) ? bq : bv) + (size_t)h * DF;

    float acc[2][8][4];
#pragma unroll
    for (int mt = 0; mt < 2; mt++)
#pragma unroll
        for (int nt = 0; nt < 8; nt++)
#pragma unroll
            for (int i = 0; i < 4; i++) acc[mt][nt][i] = 0.f;

    mm_mainloop<50>(A + (size_t)m0 * DF, DF, B + (size_t)n0 * DF, DF,
                    smemBase, tid, acc);

    const int lane = tid & 31, w = tid >> 5;
    const int g = lane >> 2, tig = lane & 3;
    const int wm = w & 3, wn = w >> 2;

    if (gg == 2) {
        float* C = g_Vp + (size_t)h * MR * DF;
#pragma unroll
        for (int mt = 0; mt < 2; mt++) {
            int row = m0 + wm * 32 + mt * 16 + g;
            float* c0 = C + (size_t)row * DF;
            float* c1 = C + (size_t)(row + 8) * DF;
#pragma unroll
            for (int nt = 0; nt < 8; nt++) {
                int col = n0 + wn * 64 + nt * 8 + tig * 2;
                if (col < DF) {
                    float b0v = bias[col], b1v = bias[col + 1];
                    *reinterpret_cast<float2*>(c0 + col) =
                        make_float2(acc[mt][nt][0] + b0v, acc[mt][nt][1] + b1v);
                    *reinterpret_cast<float2*>(c1 + col) =
                        make_float2(acc[mt][nt][2] + b0v, acc[mt][nt][3] + b1v);
                }
            }
        }
    } else {
        float* D = (gg == 0) ? g_Ks : g_Qs;
#pragma unroll
        for (int mt = 0; mt < 2; mt++) {
            int row = m0 + wm * 32 + mt * 16 + g;      // global m = n*256 + q
            int q  = row & 255;
            size_t b0r = ((size_t)(((row >> 8) << 3) + h) * 256 + q) * DF;
            size_t b1r = b0r + 8 * (size_t)DF;          // row+8: same n-block, same parity
#pragma unroll
            for (int nt = 0; nt < 8; nt++) {
                int col = n0 + wn * 64 + nt * 8 + tig * 2;
                if (col < DF) {
                    float b0v = bias[col], b1v = bias[col + 1];
                    int s0 = shufpos(col, q & 7), s1 = shufpos(col + 1, q & 7);
                    D[b0r + s0] = tf32r(acc[mt][nt][0] + b0v);
                    D[b0r + s1] = tf32r(acc[mt][nt][1] + b1v);
                    D[b1r + s0] = tf32r(acc[mt][nt][2] + b0v);
                    D[b1r + s1] = tf32r(acc[mt][nt][3] + b1v);
                }
            }
        }
    }
}

// ---------------- kernel 2b: V -> V^T shuffled tf32 -------------------------
__global__ void transpose_v() {
    const int z = blockIdx.z;                 // h*32 + n
    const int h = z >> 5, n = z & 31;
    const int t0 = blockIdx.x * 32, d0 = blockIdx.y * 32;
    __shared__ float tl[32][33];
    const float* Vp = g_Vp + (size_t)h * MR * DF + (size_t)(n * 256) * DF;
#pragma unroll
    for (int i = threadIdx.y; i < 32; i += 8)
        tl[i][threadIdx.x] = Vp[(size_t)(t0 + i) * DF + d0 + threadIdx.x];
    __syncthreads();
    float* Vt = g_Vts + (size_t)z * NPADW * TT;
#pragma unroll
    for (int i = threadIdx.y; i < 32; i += 8) {
        int d = d0 + i, t = t0 + threadIdx.x;
        Vt[(size_t)d * TT + shufpos(t, d & 7)] = tf32r(tl[threadIdx.x][i]);
    }
}

// ---------------- kernel 3: scores S = scale * Q K^T (tf32 mma) -------------
__global__ __launch_bounds__(256, 2)
void gemm_scores_mma() {
    extern __shared__ char dsm[];
    const uint32_t smemBase = (uint32_t)__cvta_generic_to_shared(dsm);
    const int tid = threadIdx.x;
    const int z = blockIdx.z;
    const int n0 = blockIdx.x * 128, m0 = blockIdx.y * 128;

    const float* tileA = g_Qs + ((size_t)z * 256 + m0) * DF;
    const float* tileB = g_Ks + ((size_t)z * 256 + n0) * DF;

    float acc[2][8][4];
#pragma unroll
    for (int mt = 0; mt < 2; mt++)
#pragma unroll
        for (int nt = 0; nt < 8; nt++)
#pragma unroll
            for (int i = 0; i < 4; i++) acc[mt][nt][i] = 0.f;

    mm_mainloop<50>(tileA, DF, tileB, DF, smemBase, tid, acc);

    const int lane = tid & 31, w = tid >> 5;
    const int g = lane >> 2, tig = lane & 3;
    const int wm = w & 3, wn = w >> 2;
    const float scale = 0.025f;
    float* Sc = g_Sp + (size_t)z * TT * TT;
#pragma unroll
    for (int mt = 0; mt < 2; mt++) {
        int q = m0 + wm * 32 + mt * 16 + g;
#pragma unroll
        for (int nt = 0; nt < 8; nt++) {
            int t = n0 + wn * 64 + nt * 8 + tig * 2;
            *reinterpret_cast<float2*>(Sc + (size_t)q * TT + t) =
                make_float2(acc[mt][nt][0] * scale, acc[mt][nt][1] * scale);
            *reinterpret_cast<float2*>(Sc + (size_t)(q + 8) * TT + t) =
                make_float2(acc[mt][nt][2] * scale, acc[mt][nt][3] * scale);
        }
    }
}

// ---------------- kernel 4: softmax over HEADS, fused shuffle+tf32 ----------
__global__ void softmax_heads() {
    int gid = blockIdx.x * blockDim.x + threadIdx.x;   // over NBATCH*T*T
    int n  = gid >> 16;
    int qt = gid & 65535;
    int q = qt >> 8, t = qt & 255;
    size_t base = ((size_t)(n * NHEADS) << 16) + qt;
    float v[NHEADS];
    float mx = -1e30f;
#pragma unroll
    for (int h = 0; h < NHEADS; h++) {
        v[h] = g_Sp[base + ((size_t)h << 16)];
        mx = fmaxf(mx, v[h]);
    }
    float s = 0.f;
#pragma unroll
    for (int h = 0; h < NHEADS; h++) { v[h] = __expf(v[h] - mx); s += v[h]; }
    float inv = 1.f / s;
    int sp = shufpos(t, q & 7);
#pragma unroll
    for (int h = 0; h < NHEADS; h++)
        g_As[((size_t)((n * NHEADS + h) * 256 + q) << 8) + sp] = tf32r(v[h] * inv);
}

// ---------------- kernel 5: Y = att @ V (tf32 mma), permuted store ----------
__global__ __launch_bounds__(256, 2)
void gemm_y_mma(float* __restrict__ out) {
    extern __shared__ char dsm[];
    const uint32_t smemBase = (uint32_t)__cvta_generic_to_shared(dsm);
    const int tid = threadIdx.x;
    const int z = blockIdx.z;
    const int n = z >> 3, h = z & 7;
    const int n0 = blockIdx.x * 128, m0 = blockIdx.y * 128;

    const float* tileA = g_As + ((size_t)z * 256 + m0) * TT;
    const float* tileB = g_Vts + ((size_t)(h * 32 + n) * NPADW + n0) * TT;

    float acc[2][8][4];
#pragma unroll
    for (int mt = 0; mt < 2; mt++)
#pragma unroll
        for (int nt = 0; nt < 8; nt++)
#pragma unroll
            for (int i = 0; i < 4; i++) acc[mt][nt][i] = 0.f;

    mm_mainloop<8>(tileA, TT, tileB, TT, smemBase, tid, acc);

    const int lane = tid & 31, w = tid >> 5;
    const int g = lane >> 2, tig = lane & 3;
    const int wm = w & 3, wn = w >> 2;
#pragma unroll
    for (int mt = 0; mt < 2; mt++) {
        int q = m0 + wm * 32 + mt * 16 + g;
#pragma unroll
        for (int nt = 0; nt < 8; nt++) {
            int d = n0 + wn * 64 + nt * 8 + tig * 2;
            if (d < DF) {
                int v = d >> 6;          // d = v*64 + c
                int c = d & 63;          // even
                size_t o = (size_t)n * (512 * TT * NV)
                         + (size_t)((c << 3) + h) * (TT * NV)
                         + (size_t)q * NV + v;
                size_t o2 = o + 8 * TT * NV;          // c+1
                out[o]                = acc[mt][nt][0];
                out[o2]               = acc[mt][nt][1];
                out[o + 8 * NV]       = acc[mt][nt][2];   // q+8
                out[o2 + 8 * NV]      = acc[mt][nt][3];
            }
        }
    }
}

// ---------------- launch ----------------------------------------------------
extern "C" void kernel_launch(void* const* d_in, const int* in_sizes, int n_in,
                              void* d_out, int out_size) {
    const float* x  = (const float*)d_in[0];
    const float* m  = (const float*)d_in[1];
    const float* Wk = (const float*)d_in[2];
    const float* bk = (const float*)d_in[3];
    const float* Wq = (const float*)d_in[4];
    const float* bq = (const float*)d_in[5];
    const float* Wv = (const float*)d_in[6];
    const float* bv = (const float*)d_in[7];
    float* out = (float*)d_out;

    cudaFuncSetAttribute(gemm_proj_mma,   cudaFuncAttributeMaxDynamicSharedMemorySize, SMEM_DYN);
    cudaFuncSetAttribute(gemm_scores_mma, cudaFuncAttributeMaxDynamicSharedMemorySize, SMEM_DYN);
    cudaFuncSetAttribute(gemm_y_mma,      cudaFuncAttributeMaxDynamicSharedMemorySize, SMEM_DYN);

    pack_kernel<<<(MR * DF) / 256, 256>>>(x, 0);
    pack_kernel<<<(MR * DF) / 256, 256>>>(m, 1);
    transpose_w<<<dim3(50, 50, 24), dim3(32, 8)>>>(Wk, Wq, Wv);

    gemm_proj_mma<<<dim3(13, 64, 24), 256, SMEM_DYN>>>(bk, bq, bv);
    transpose_v<<<dim3(8, 50, 256), dim3(32, 8)>>>();

    gemm_scores_mma<<<dim3(2, 2, 256), 256, SMEM_DYN>>>();
    softmax_heads<<<(NBATCH * TT * TT) / 256, 256>>>();
    gemm_y_mma<<<dim3(13, 2, 256), 256, SMEM_DYN>>>(out);
}